// round 13
// baseline (speedup 1.0000x reference)
#include <cuda_runtime.h>
#include <cstdint>

// Problem constants
#define T_STEPS 512
#define HDIM    128
#define G4      512     // 4*H
#define OUTD    64
#define BSEL    255     // only batch row that affects the output
#define NCTA    8
#define SLICEF  20      // 16 floats + 4 pad per column-slice (bank spread)
#define HBUF    (8 * SLICEF)   // one h buffer = 160 floats (128 elements)

// ---------------- scratch (no allocations allowed) ----------------
__device__ float g_xg[T_STEPS * G4];     // precomputed input gates for batch 255
__device__ float g_hout[256 * HDIM];     // h[255, 256+j, :]
__device__ float g_Wc[OUTD * HDIM];      // W2 @ W1
__device__ float g_bc[OUTD];             // W2 @ b1 + b2

// ---------------- helpers ----------------
__device__ __forceinline__ float tanh_mufu(float x) {
    float y;
    asm("tanh.approx.f32 %0, %1;" : "=f"(y) : "f"(x));
    return y;
}
__device__ __forceinline__ float sigmoid_mufu(float x) {
    return fmaf(0.5f, tanh_mufu(0.5f * x), 0.5f);
}
__device__ __forceinline__ void fma_f32x2(unsigned long long& acc,
                                          unsigned long long a,
                                          unsigned long long b) {
    asm("fma.rn.f32x2 %0, %1, %2, %0;" : "+l"(acc) : "l"(a), "l"(b));
}
__device__ __forceinline__ unsigned long long add_f32x2(unsigned long long a,
                                                        unsigned long long b) {
    unsigned long long r;
    asm("add.rn.f32x2 %0, %1, %2;" : "=l"(r) : "l"(a), "l"(b));
    return r;
}
__device__ __forceinline__ uint32_t smem_u32(const void* p) {
    uint32_t a;
    asm("{ .reg .u64 t; cvta.to.shared.u64 t, %1; cvt.u32.u64 %0, t; }"
        : "=r"(a) : "l"(p));
    return a;
}
#define CLUSTER_SYNC() do { \
    asm volatile("barrier.cluster.arrive.aligned;" ::: "memory"); \
    asm volatile("barrier.cluster.wait.aligned;"   ::: "memory"); \
} while (0)
#define CLUSTER_ARRIVE() asm volatile("barrier.cluster.arrive.aligned;" ::: "memory")
#define CLUSTER_WAIT()   asm volatile("barrier.cluster.wait.aligned;"   ::: "memory")

// ---------------- kernel 1 (merged): xg for all t  +  MLP collapse
// blocks 0..63: xg[t, j] = W_ih[j,:] . x[255,t,:] + b_ih[j] + b_hh[j]
// block 64:     Wc = W2 @ W1, bc = W2 @ b1 + b2
__global__ void __launch_bounds__(512) side_kernel(
    const float* __restrict__ x, const float* __restrict__ Wih,
    const float* __restrict__ bih, const float* __restrict__ bhh,
    const float* __restrict__ W1, const float* __restrict__ b1,
    const float* __restrict__ W2, const float* __restrict__ b2)
{
    int tid = threadIdx.x;
    if (blockIdx.x < 64) {
        __shared__ __align__(16) float xs[8][HDIM];
        int t0 = blockIdx.x * 8;

        for (int i = tid; i < 8 * HDIM; i += 512) {
            int tt = i >> 7, d = i & 127;
            xs[tt][d] = x[((size_t)BSEL * T_STEPS + t0 + tt) * HDIM + d];
        }
        __syncthreads();

        const float4* wr4 = reinterpret_cast<const float4*>(Wih + tid * HDIM);
        float acc[8];
        #pragma unroll
        for (int tt = 0; tt < 8; tt++) acc[tt] = 0.0f;

        #pragma unroll
        for (int q = 0; q < HDIM / 4; q++) {
            float4 w = wr4[q];
            #pragma unroll
            for (int tt = 0; tt < 8; tt++) {
                float4 xv = reinterpret_cast<const float4*>(xs[tt])[q];
                acc[tt] += w.x * xv.x + w.y * xv.y + w.z * xv.z + w.w * xv.w;
            }
        }
        float bb = bih[tid] + bhh[tid];
        #pragma unroll
        for (int tt = 0; tt < 8; tt++)
            g_xg[(t0 + tt) * G4 + tid] = acc[tt] + bb;
    } else {
        // MLP collapse (one block)
        for (int idx = tid; idx < OUTD * HDIM; idx += 512) {
            int o = idx >> 7, hh = idx & 127;
            float acc = 0.0f;
            #pragma unroll 4
            for (int m = 0; m < HDIM; m++)
                acc += W2[o * HDIM + m] * W1[m * HDIM + hh];
            g_Wc[idx] = acc;
        }
        if (tid < OUTD) {
            float acc = b2[tid];
            #pragma unroll 4
            for (int m = 0; m < HDIM; m++)
                acc += W2[tid * HDIM + m] * b1[m];
            g_bc[tid] = acc;
        }
    }
}

// ---------------- kernel 2: sequential LSTM scan (batch 255 only)
// 8-CTA cluster, 256 threads each. Thread tid: eL = tid>>4 (this CTA's 16
// elements), sub = tid&15: gp = sub&1 (gate pair), q = sub>>1 (16-col slice).
// Each thread: 2 gate rows x 16 cols = 16 reg-resident u64 weights,
// 16 FMA2/step, 4 LDS.128. Butterfly xor2+xor4+xor8 over slices, xor1 swap
// for gate pairs. MUFU gates. DISTRIBUTED peer stores: lanes sub 0..7 of each
// element group each store h to ONE cluster CTA (peer = (rank+sub)&7);
// lane sub==8 does the g_hout global store. One split CLUSTER_SYNC per step.
__global__ void __cluster_dims__(NCTA, 1, 1) __launch_bounds__(256, 1)
lstm_scan_kernel(const float* __restrict__ Whh)
{
    __shared__ __align__(16) float h_smem[2 * HBUF];

    int tid = threadIdx.x;
    unsigned rank;
    asm("mov.u32 %0, %%cluster_ctarank;" : "=r"(rank));

    int sub = tid & 15;
    int eL  = tid >> 4;            // 0..15
    int gp  = sub & 1;
    int q   = sub >> 1;            // 0..7, 16-col slice
    int e   = (int)rank * 16 + eL; // global hidden element

    // register-resident weights: 2 gates x 8 u64 (cols q*16 .. q*16+15)
    unsigned long long w2[2][8];
    #pragma unroll
    for (int gl = 0; gl < 2; gl++) {
        const unsigned long long* wsrc = reinterpret_cast<const unsigned long long*>(
            Whh + (size_t)((2 * gp + gl) * HDIM + e) * HDIM + q * 16);
        #pragma unroll
        for (int k = 0; k < 8; k++) w2[gl][k] = wsrc[k];
    }

    uint32_t hbase = smem_u32(h_smem);
    // this lane's store destination CTA (only lanes sub<8 store)
    uint32_t dstbase = hbase;
    if (sub < 8) {
        unsigned peer = (rank + (unsigned)sub) & (NCTA - 1);
        asm("mapa.shared::cluster.u32 %0, %1, %2;"
            : "=r"(dstbase) : "r"(hbase), "r"(peer));
    }

    // zero both h buffers (t=0 input must be zero everywhere)
    for (int i = tid; i < 2 * HBUF; i += 256) h_smem[i] = 0.0f;
    __syncthreads();
    CLUSTER_SYNC();

    // padded slot of element e in an h buffer (slice e>>4, pos e&15)
    uint32_t woff = (uint32_t)(((e >> 4) * SLICEF + (e & 15)) * 4);

    float c = 0.0f;                 // identical across the 16 lanes of the group
    const float* xg_a = g_xg + (2 * gp) * HDIM + e;
    const float* xg_b = g_xg + (2 * gp + 1) * HDIM + e;

    // software-pipelined xg (only q==0 lanes contribute)
    float xa = 0.0f, xb = 0.0f;
    if (q == 0) { xa = __ldg(xg_a); xb = __ldg(xg_b); }

    for (int t = 0; t < T_STEPS; t++) {
        // 16 h floats of slice q: 4 LDS.128 -> 8 u64
        const ulonglong2* hp2 = reinterpret_cast<const ulonglong2*>(
            h_smem + (t & 1) * HBUF + q * SLICEF);
        unsigned long long hreg[8];
        #pragma unroll
        for (int k = 0; k < 4; k++) {
            ulonglong2 v = hp2[k];
            hreg[2 * k] = v.x;
            hreg[2 * k + 1] = v.y;
        }

        // 2 gate partial dots over the 16-col slice
        float p0, p1;
        {
            unsigned long long a0 = 0ull, a1 = 0ull, b0 = 0ull, b1 = 0ull;
            #pragma unroll
            for (int k = 0; k < 8; k += 2) {
                fma_f32x2(a0, w2[0][k],     hreg[k]);
                fma_f32x2(a1, w2[0][k + 1], hreg[k + 1]);
                fma_f32x2(b0, w2[1][k],     hreg[k]);
                fma_f32x2(b1, w2[1][k + 1], hreg[k + 1]);
            }
            unsigned long long sA = add_f32x2(a0, a1);
            unsigned long long sB = add_f32x2(b0, b1);
            float sx, sy;
            asm("mov.b64 {%0,%1}, %2;" : "=f"(sx), "=f"(sy) : "l"(sA));
            p0 = sx + sy;
            asm("mov.b64 {%0,%1}, %2;" : "=f"(sx), "=f"(sy) : "l"(sB));
            p1 = sx + sy;
        }
        p0 += xa;
        p1 += xb;

        // sum over the 8 slices (lane bits 1..3), then swap gate pairs (bit 0)
        p0 += __shfl_xor_sync(0xFFFFFFFFu, p0, 2);
        p1 += __shfl_xor_sync(0xFFFFFFFFu, p1, 2);
        p0 += __shfl_xor_sync(0xFFFFFFFFu, p0, 4);
        p1 += __shfl_xor_sync(0xFFFFFFFFu, p1, 4);
        p0 += __shfl_xor_sync(0xFFFFFFFFu, p0, 8);
        p1 += __shfl_xor_sync(0xFFFFFFFFu, p1, 8);
        float o0 = __shfl_xor_sync(0xFFFFFFFFu, p0, 1);
        float o1 = __shfl_xor_sync(0xFFFFFFFFu, p1, 1);
        float gi = (gp == 0) ? p0 : o0;
        float gf = (gp == 0) ? p1 : o1;
        float gg = (gp == 0) ? o0 : p0;
        float go = (gp == 0) ? o1 : p1;

        // gate math via MUFU.TANH (redundant in all 16 lanes, no divergence)
        float iv = sigmoid_mufu(gi);
        float fv = sigmoid_mufu(gf);
        float gv = tanh_mufu(gg);
        float ov = sigmoid_mufu(go);
        c = fv * c + iv * gv;
        float h = ov * tanh_mufu(c);

        // distributed store: lanes sub 0..7 each write h to one CTA's buffer
        uint32_t off = ((t + 1) & 1) * (HBUF * 4) + woff;
        if (sub < 8) {
            asm volatile("st.shared::cluster.f32 [%0], %1;"
                         :: "r"(dstbase + off), "f"(h) : "memory");
        }

        // split barrier: arrive now, hide gmem traffic, wait last
        CLUSTER_ARRIVE();

        if (sub == 8 && t >= 256) g_hout[(t - 256) * HDIM + e] = h;
        int tn = (t + 1 < T_STEPS) ? (t + 1) : t;
        if (q == 0) {
            xa = __ldg(xg_a + tn * G4);
            xb = __ldg(xg_b + tn * G4);
        }

        CLUSTER_WAIT();
    }
}

// ---------------- kernel 3: out[j, o] = bc[o] + Wc[o,:] . h[255, 256+j, :]
// 32 blocks x 512 threads: 8 j's per block, thread = (jj, o).
__global__ void __launch_bounds__(512) mlp_final_kernel(float* __restrict__ out)
{
    __shared__ __align__(16) float hs[8][HDIM];
    int tid = threadIdx.x;
    int jb  = blockIdx.x * 8;
    int jj  = tid >> 6;
    int o   = tid & 63;

    for (int i = tid; i < 8 * HDIM; i += 512)
        hs[i >> 7][i & 127] = g_hout[(jb + (i >> 7)) * HDIM + (i & 127)];
    __syncthreads();

    const float4* wr4 = reinterpret_cast<const float4*>(g_Wc + o * HDIM);
    const float4* hv4 = reinterpret_cast<const float4*>(hs[jj]);
    float a0 = 0.0f, a1 = 0.0f;
    #pragma unroll
    for (int qq = 0; qq < HDIM / 4; qq += 2) {
        float4 w0 = wr4[qq],     v0 = hv4[qq];
        float4 w1 = wr4[qq + 1], v1 = hv4[qq + 1];
        a0 += w0.x * v0.x + w0.y * v0.y + w0.z * v0.z + w0.w * v0.w;
        a1 += w1.x * v1.x + w1.y * v1.y + w1.z * v1.z + w1.w * v1.w;
    }
    out[(jb + jj) * OUTD + o] = g_bc[o] + a0 + a1;
}

// ---------------- launch ----------------
extern "C" void kernel_launch(void* const* d_in, const int* in_sizes, int n_in,
                              void* d_out, int out_size)
{
    const float* x   = (const float*)d_in[0];
    const float* Wih = (const float*)d_in[1];
    const float* Whh = (const float*)d_in[2];
    const float* bih = (const float*)d_in[3];
    const float* bhh = (const float*)d_in[4];
    const float* W1  = (const float*)d_in[5];
    const float* b1  = (const float*)d_in[6];
    const float* W2  = (const float*)d_in[7];
    const float* b2  = (const float*)d_in[8];
    float* out = (float*)d_out;

    side_kernel<<<65, 512>>>(x, Wih, bih, bhh, W1, b1, W2, b2);
    lstm_scan_kernel<<<NCTA, 256>>>(Whh);
    mlp_final_kernel<<<32, 512>>>(out);
}

// round 14
// speedup vs baseline: 1.1347x; 1.1347x over previous
#include <cuda_runtime.h>
#include <cstdint>

// Problem constants
#define T_STEPS 512
#define HDIM    128
#define G4      512     // 4*H
#define OUTD    64
#define BSEL    255     // only batch row that affects the output
#define NCTA    8
#define SLICEF  20      // 16 floats + 4 pad per column-slice (bank spread)
#define HBUF    (8 * SLICEF)   // one h buffer = 160 floats (128 elements)

// ---------------- scratch (no allocations allowed) ----------------
__device__ float g_xg[T_STEPS * G4];     // precomputed input gates for batch 255
__device__ float g_hout[256 * HDIM];     // h[255, 256+j, :]
__device__ float g_Wc[OUTD * HDIM];      // W2 @ W1
__device__ float g_bc[OUTD];             // W2 @ b1 + b2

// ---------------- helpers ----------------
__device__ __forceinline__ float tanh_mufu(float x) {
    float y;
    asm("tanh.approx.f32 %0, %1;" : "=f"(y) : "f"(x));
    return y;
}
__device__ __forceinline__ float sigmoid_mufu(float x) {
    return fmaf(0.5f, tanh_mufu(0.5f * x), 0.5f);
}
__device__ __forceinline__ void fma_f32x2(unsigned long long& acc,
                                          unsigned long long a,
                                          unsigned long long b) {
    asm("fma.rn.f32x2 %0, %1, %2, %0;" : "+l"(acc) : "l"(a), "l"(b));
}
__device__ __forceinline__ unsigned long long add_f32x2(unsigned long long a,
                                                        unsigned long long b) {
    unsigned long long r;
    asm("add.rn.f32x2 %0, %1, %2;" : "=l"(r) : "l"(a), "l"(b));
    return r;
}
__device__ __forceinline__ uint32_t smem_u32(const void* p) {
    uint32_t a;
    asm("{ .reg .u64 t; cvta.to.shared.u64 t, %1; cvt.u32.u64 %0, t; }"
        : "=r"(a) : "l"(p));
    return a;
}
#define CLUSTER_SYNC() do { \
    asm volatile("barrier.cluster.arrive.aligned;" ::: "memory"); \
    asm volatile("barrier.cluster.wait.aligned;"   ::: "memory"); \
} while (0)
#define CLUSTER_ARRIVE() asm volatile("barrier.cluster.arrive.aligned;" ::: "memory")
#define CLUSTER_WAIT()   asm volatile("barrier.cluster.wait.aligned;"   ::: "memory")

// ---------------- kernel 1: xg (blocks 0..63) + MLP collapse (blocks 64..79)
__global__ void __launch_bounds__(512) side_kernel(
    const float* __restrict__ x, const float* __restrict__ Wih,
    const float* __restrict__ bih, const float* __restrict__ bhh,
    const float* __restrict__ W1, const float* __restrict__ b1,
    const float* __restrict__ W2, const float* __restrict__ b2)
{
    int tid = threadIdx.x;
    if (blockIdx.x < 64) {
        __shared__ __align__(16) float xs[8][HDIM];
        int t0 = blockIdx.x * 8;

        for (int i = tid; i < 8 * HDIM; i += 512) {
            int tt = i >> 7, d = i & 127;
            xs[tt][d] = x[((size_t)BSEL * T_STEPS + t0 + tt) * HDIM + d];
        }
        __syncthreads();

        const float4* wr4 = reinterpret_cast<const float4*>(Wih + tid * HDIM);
        float acc[8];
        #pragma unroll
        for (int tt = 0; tt < 8; tt++) acc[tt] = 0.0f;

        #pragma unroll
        for (int q = 0; q < HDIM / 4; q++) {
            float4 w = wr4[q];
            #pragma unroll
            for (int tt = 0; tt < 8; tt++) {
                float4 xv = reinterpret_cast<const float4*>(xs[tt])[q];
                acc[tt] += w.x * xv.x + w.y * xv.y + w.z * xv.z + w.w * xv.w;
            }
        }
        float bb = bih[tid] + bhh[tid];
        #pragma unroll
        for (int tt = 0; tt < 8; tt++)
            g_xg[(t0 + tt) * G4 + tid] = acc[tt] + bb;
    } else {
        // MLP collapse, spread over 16 blocks (one output element per thread)
        int idx = (blockIdx.x - 64) * 512 + tid;
        if (idx < OUTD * HDIM) {
            int o = idx >> 7, hh = idx & 127;
            float acc = 0.0f;
            #pragma unroll 4
            for (int m = 0; m < HDIM; m++)
                acc += W2[o * HDIM + m] * W1[m * HDIM + hh];
            g_Wc[idx] = acc;
        }
        if (idx < OUTD) {
            float acc = b2[idx];
            #pragma unroll 4
            for (int m = 0; m < HDIM; m++)
                acc += W2[idx * HDIM + m] * b1[m];
            g_bc[idx] = acc;
        }
    }
}

// ---------------- kernel 2: sequential LSTM scan (batch 255 only)
// 8-CTA cluster, 256 threads each (unchanged from R13 — measured ~308 us).
// Thread tid: eL = tid>>4 (this CTA's 16 elements), sub = tid&15:
//   gp = sub&1 (gate pair), q = sub>>1 (16-col slice).
// 2 gate rows x 16 cols = 16 reg-resident u64 weights, 16 FMA2/step,
// 4 LDS.128. Butterfly xor2+xor4+xor8 over slices, xor1 gate-pair swap.
// MUFU gates. Distributed peer stores (lane sub<8 -> CTA (rank+sub)&7);
// lane sub==8 does the g_hout store. One split CLUSTER_SYNC per step.
__global__ void __cluster_dims__(NCTA, 1, 1) __launch_bounds__(256, 1)
lstm_scan_kernel(const float* __restrict__ Whh)
{
    __shared__ __align__(16) float h_smem[2 * HBUF];

    int tid = threadIdx.x;
    unsigned rank;
    asm("mov.u32 %0, %%cluster_ctarank;" : "=r"(rank));

    int sub = tid & 15;
    int eL  = tid >> 4;            // 0..15
    int gp  = sub & 1;
    int q   = sub >> 1;            // 0..7, 16-col slice
    int e   = (int)rank * 16 + eL; // global hidden element

    // register-resident weights: 2 gates x 8 u64 (cols q*16 .. q*16+15)
    unsigned long long w2[2][8];
    #pragma unroll
    for (int gl = 0; gl < 2; gl++) {
        const unsigned long long* wsrc = reinterpret_cast<const unsigned long long*>(
            Whh + (size_t)((2 * gp + gl) * HDIM + e) * HDIM + q * 16);
        #pragma unroll
        for (int k = 0; k < 8; k++) w2[gl][k] = wsrc[k];
    }

    uint32_t hbase = smem_u32(h_smem);
    // this lane's store destination CTA (only lanes sub<8 store)
    uint32_t dstbase = hbase;
    if (sub < 8) {
        unsigned peer = (rank + (unsigned)sub) & (NCTA - 1);
        asm("mapa.shared::cluster.u32 %0, %1, %2;"
            : "=r"(dstbase) : "r"(hbase), "r"(peer));
    }

    // zero both h buffers (t=0 input must be zero everywhere)
    for (int i = tid; i < 2 * HBUF; i += 256) h_smem[i] = 0.0f;
    __syncthreads();
    CLUSTER_SYNC();

    // padded slot of element e in an h buffer (slice e>>4, pos e&15)
    uint32_t woff = (uint32_t)(((e >> 4) * SLICEF + (e & 15)) * 4);

    float c = 0.0f;                 // identical across the 16 lanes of the group
    const float* xg_a = g_xg + (2 * gp) * HDIM + e;
    const float* xg_b = g_xg + (2 * gp + 1) * HDIM + e;

    // software-pipelined xg (only q==0 lanes contribute)
    float xa = 0.0f, xb = 0.0f;
    if (q == 0) { xa = __ldg(xg_a); xb = __ldg(xg_b); }

    for (int t = 0; t < T_STEPS; t++) {
        // 16 h floats of slice q: 4 LDS.128 -> 8 u64
        const ulonglong2* hp2 = reinterpret_cast<const ulonglong2*>(
            h_smem + (t & 1) * HBUF + q * SLICEF);
        unsigned long long hreg[8];
        #pragma unroll
        for (int k = 0; k < 4; k++) {
            ulonglong2 v = hp2[k];
            hreg[2 * k] = v.x;
            hreg[2 * k + 1] = v.y;
        }

        // 2 gate partial dots over the 16-col slice
        float p0, p1;
        {
            unsigned long long a0 = 0ull, a1 = 0ull, b0 = 0ull, b1 = 0ull;
            #pragma unroll
            for (int k = 0; k < 8; k += 2) {
                fma_f32x2(a0, w2[0][k],     hreg[k]);
                fma_f32x2(a1, w2[0][k + 1], hreg[k + 1]);
                fma_f32x2(b0, w2[1][k],     hreg[k]);
                fma_f32x2(b1, w2[1][k + 1], hreg[k + 1]);
            }
            unsigned long long sA = add_f32x2(a0, a1);
            unsigned long long sB = add_f32x2(b0, b1);
            float sx, sy;
            asm("mov.b64 {%0,%1}, %2;" : "=f"(sx), "=f"(sy) : "l"(sA));
            p0 = sx + sy;
            asm("mov.b64 {%0,%1}, %2;" : "=f"(sx), "=f"(sy) : "l"(sB));
            p1 = sx + sy;
        }
        p0 += xa;
        p1 += xb;

        // sum over the 8 slices (lane bits 1..3), then swap gate pairs (bit 0)
        p0 += __shfl_xor_sync(0xFFFFFFFFu, p0, 2);
        p1 += __shfl_xor_sync(0xFFFFFFFFu, p1, 2);
        p0 += __shfl_xor_sync(0xFFFFFFFFu, p0, 4);
        p1 += __shfl_xor_sync(0xFFFFFFFFu, p1, 4);
        p0 += __shfl_xor_sync(0xFFFFFFFFu, p0, 8);
        p1 += __shfl_xor_sync(0xFFFFFFFFu, p1, 8);
        float o0 = __shfl_xor_sync(0xFFFFFFFFu, p0, 1);
        float o1 = __shfl_xor_sync(0xFFFFFFFFu, p1, 1);
        float gi = (gp == 0) ? p0 : o0;
        float gf = (gp == 0) ? p1 : o1;
        float gg = (gp == 0) ? o0 : p0;
        float go = (gp == 0) ? o1 : p1;

        // gate math via MUFU.TANH (redundant in all 16 lanes, no divergence)
        float iv = sigmoid_mufu(gi);
        float fv = sigmoid_mufu(gf);
        float gv = tanh_mufu(gg);
        float ov = sigmoid_mufu(go);
        c = fv * c + iv * gv;
        float h = ov * tanh_mufu(c);

        // distributed store: lanes sub 0..7 each write h to one CTA's buffer
        uint32_t off = ((t + 1) & 1) * (HBUF * 4) + woff;
        if (sub < 8) {
            asm volatile("st.shared::cluster.f32 [%0], %1;"
                         :: "r"(dstbase + off), "f"(h) : "memory");
        }

        // split barrier: arrive now, hide gmem traffic, wait last
        CLUSTER_ARRIVE();

        if (sub == 8 && t >= 256) g_hout[(t - 256) * HDIM + e] = h;
        int tn = (t + 1 < T_STEPS) ? (t + 1) : t;
        if (q == 0) {
            xa = __ldg(xg_a + tn * G4);
            xb = __ldg(xg_b + tn * G4);
        }

        CLUSTER_WAIT();
    }
}

// ---------------- kernel 3: out[j, o] = bc[o] + Wc[o,:] . h[255, 256+j, :]
// 32 blocks x 512 threads: 8 j's per block, thread = (jj, o).
__global__ void __launch_bounds__(512) mlp_final_kernel(float* __restrict__ out)
{
    __shared__ __align__(16) float hs[8][HDIM];
    int tid = threadIdx.x;
    int jb  = blockIdx.x * 8;
    int jj  = tid >> 6;
    int o   = tid & 63;

    for (int i = tid; i < 8 * HDIM; i += 512)
        hs[i >> 7][i & 127] = g_hout[(jb + (i >> 7)) * HDIM + (i & 127)];
    __syncthreads();

    const float4* wr4 = reinterpret_cast<const float4*>(g_Wc + o * HDIM);
    const float4* hv4 = reinterpret_cast<const float4*>(hs[jj]);
    float a0 = 0.0f, a1 = 0.0f;
    #pragma unroll
    for (int qq = 0; qq < HDIM / 4; qq += 2) {
        float4 w0 = wr4[qq],     v0 = hv4[qq];
        float4 w1 = wr4[qq + 1], v1 = hv4[qq + 1];
        a0 += w0.x * v0.x + w0.y * v0.y + w0.z * v0.z + w0.w * v0.w;
        a1 += w1.x * v1.x + w1.y * v1.y + w1.z * v1.z + w1.w * v1.w;
    }
    out[(jb + jj) * OUTD + o] = g_bc[o] + a0 + a1;
}

// ---------------- launch ----------------
extern "C" void kernel_launch(void* const* d_in, const int* in_sizes, int n_in,
                              void* d_out, int out_size)
{
    const float* x   = (const float*)d_in[0];
    const float* Wih = (const float*)d_in[1];
    const float* Whh = (const float*)d_in[2];
    const float* bih = (const float*)d_in[3];
    const float* bhh = (const float*)d_in[4];
    const float* W1  = (const float*)d_in[5];
    const float* b1  = (const float*)d_in[6];
    const float* W2  = (const float*)d_in[7];
    const float* b2  = (const float*)d_in[8];
    float* out = (float*)d_out;

    side_kernel<<<80, 512>>>(x, Wih, bih, bhh, W1, b1, W2, b2);
    lstm_scan_kernel<<<NCTA, 256>>>(Whh);
    mlp_final_kernel<<<32, 512>>>(out);
}